// round 6
// baseline (speedup 1.0000x reference)
#include <cuda_runtime.h>
#include <math.h>

// ---------------------------------------------------------------------------
// RowWiseGatedAttention — tf32 mma.sync + ldmatrix attention.
// B=1, c_m=256, s=128, i=256, H=8, c_head=32, c_z=128.
// ---------------------------------------------------------------------------

#define CM     256
#define S_DIM  128
#define I_DIM  256
#define NCOL   32768            // S_DIM * I_DIM
#define CZ     128
#define IJ     65536            // I_DIM * I_DIM
#define NH     8
#define NTOT   8388608          // CM*NCOL == CZ*IJ
#define LN_EPS 1e-5f

// ---------------- scratch (static device globals; no allocation) -----------
__device__ unsigned g_x[(size_t)CM * NCOL];        // LN1(msa), tf32 bits [c][s*i]
__device__ float    g_qkvg[(size_t)4 * CM * NCOL]; // q,k,v (tf32-rounded), g (fp32)
__device__ float    g_bias[(size_t)NH * IJ];       // pair bias [h][i*j]
__device__ float    g_o[(size_t)CM * NCOL];        // gated attn out (tf32-rounded)
__device__ unsigned g_wstack[1024 * 256];          // Wq,Wk,Wv,Wg tf32 bits
__device__ unsigned g_wrep[256 * 256];             // Wrep tf32 bits
__device__ float2   g_part[2][1024];
__device__ float    g_stats[4];

// ---------------- tf32 / mma / ldmatrix helpers -----------------------------
__device__ __forceinline__ unsigned f2tf(float x) {
    unsigned r; asm("cvt.rna.tf32.f32 %0, %1;" : "=r"(r) : "f"(x)); return r;
}
__device__ __forceinline__ void mma_tf32(float* c, unsigned a0, unsigned a1,
                                         unsigned a2, unsigned a3,
                                         unsigned b0, unsigned b1) {
    asm volatile(
        "mma.sync.aligned.m16n8k8.row.col.f32.tf32.tf32.f32 "
        "{%0,%1,%2,%3}, {%4,%5,%6,%7}, {%8,%9}, {%0,%1,%2,%3};"
        : "+f"(c[0]), "+f"(c[1]), "+f"(c[2]), "+f"(c[3])
        : "r"(a0), "r"(a1), "r"(a2), "r"(a3), "r"(b0), "r"(b1));
}
__device__ __forceinline__ void cpa16(unsigned saddr, const void* g) {
    asm volatile("cp.async.ca.shared.global [%0], [%1], 16;" :: "r"(saddr), "l"(g));
}
__device__ __forceinline__ void ldsm_x4(unsigned& r0, unsigned& r1,
                                        unsigned& r2, unsigned& r3, unsigned addr) {
    asm volatile("ldmatrix.sync.aligned.m8n8.x4.shared.b16 {%0,%1,%2,%3}, [%4];"
                 : "=r"(r0), "=r"(r1), "=r"(r2), "=r"(r3) : "r"(addr));
}
// A-fragment (m16 x k8) address for this lane: base over [row][stride] tf32 array
__device__ __forceinline__ unsigned lds_addr_a(unsigned base, int row0, int col, int stride) {
    int lane = threadIdx.x & 31;
    int g = lane >> 3, lr = lane & 7;
    int row = row0 + lr + ((g & 1) << 3);
    int c = col + ((g >> 1) << 2);
    return base + (unsigned)((row * stride + c) << 2);
}
// B-fragment (n8 x k16) address: array is [n][k] (row-major over k)
__device__ __forceinline__ unsigned lds_addr_b(unsigned base, int n0, int k0, int stride) {
    int lane = threadIdx.x & 31;
    int g = lane >> 3, lr = lane & 7;
    return base + (unsigned)(((n0 + lr) * stride + k0 + (g << 2)) << 2);
}

// ---------------- merged pre-pass: weight cvt + both partial reductions -----
__global__ void __launch_bounds__(256) k_pre(const float* __restrict__ msa,
                                             const float* __restrict__ pair,
                                             const float* __restrict__ Wq,
                                             const float* __restrict__ Wk,
                                             const float* __restrict__ Wv,
                                             const float* __restrict__ Wg,
                                             const float* __restrict__ Wrep) {
    int bid = blockIdx.x;
    if (bid >= 2048) {               // weight conversion blocks
        int t = (bid - 2048) * 256 + threadIdx.x;    // 0..327679
        if (t < 262144) {
            int sel = t >> 16, off = t & 65535;
            const float* W = (sel == 0) ? Wq : (sel == 1) ? Wk : (sel == 2) ? Wv : Wg;
            g_wstack[t] = f2tf(W[off]);
        } else {
            int off = t - 262144;
            g_wrep[off] = f2tf(Wrep[off]);
        }
        return;
    }
    int which = bid >> 10;
    const float4* s4 = (const float4*)(which ? pair : msa);
    int t = (bid & 1023) * 256 + threadIdx.x;
    float s = 0.f, ss = 0.f;
#pragma unroll
    for (int k = 0; k < 8; k++) {
        float4 v = s4[t + k * 262144];
        s  += v.x + v.y + v.z + v.w;
        ss += v.x * v.x + v.y * v.y + v.z * v.z + v.w * v.w;
    }
    __shared__ float sh[256], sh2[256];
    int tid = threadIdx.x;
    sh[tid] = s; sh2[tid] = ss;
    __syncthreads();
    for (int off = 128; off; off >>= 1) {
        if (tid < off) { sh[tid] += sh[tid + off]; sh2[tid] += sh2[tid + off]; }
        __syncthreads();
    }
    if (tid == 0) g_part[which][bid & 1023] = make_float2(sh[0], sh2[0]);
}

// ---------------- finalize stats (shuffle-based) -----------------------------
__global__ void __launch_bounds__(1024) k_finalize() {
    int t = threadIdx.x, lane = t & 31, w = t >> 5;
    float2 pa = g_part[0][t];
    float2 pb = g_part[1][t];
    float v0 = pa.x, v1 = pa.y, v2 = pb.x, v3 = pb.y;
#pragma unroll
    for (int off = 16; off; off >>= 1) {
        v0 += __shfl_xor_sync(0xffffffffu, v0, off);
        v1 += __shfl_xor_sync(0xffffffffu, v1, off);
        v2 += __shfl_xor_sync(0xffffffffu, v2, off);
        v3 += __shfl_xor_sync(0xffffffffu, v3, off);
    }
    __shared__ float sm[4][32];
    if (lane == 0) { sm[0][w] = v0; sm[1][w] = v1; sm[2][w] = v2; sm[3][w] = v3; }
    __syncthreads();
    if (w == 0) {
        v0 = sm[0][lane]; v1 = sm[1][lane]; v2 = sm[2][lane]; v3 = sm[3][lane];
#pragma unroll
        for (int off = 16; off; off >>= 1) {
            v0 += __shfl_xor_sync(0xffffffffu, v0, off);
            v1 += __shfl_xor_sync(0xffffffffu, v1, off);
            v2 += __shfl_xor_sync(0xffffffffu, v2, off);
            v3 += __shfl_xor_sync(0xffffffffu, v3, off);
        }
        if (lane == 0) {
            const float invN = 1.f / (float)NTOT;
            float mu1 = v0 * invN, var1 = v1 * invN - mu1 * mu1;
            float mu2 = v2 * invN, var2 = v3 * invN - mu2 * mu2;
            g_stats[0] = mu1; g_stats[1] = rsqrtf(var1 + LN_EPS);
            g_stats[2] = mu2; g_stats[3] = rsqrtf(var2 + LN_EPS);
        }
    }
}

// ---------------- merged LN1 apply + pair-bias GEMV -------------------------
__global__ void __launch_bounds__(256) k_ln1bias(const float* __restrict__ msa,
                                                 const float* __restrict__ w,
                                                 const float* __restrict__ b,
                                                 const float* __restrict__ pair,
                                                 const float* __restrict__ ln2w,
                                                 const float* __restrict__ ln2b,
                                                 const float* __restrict__ Wb) {
    int bid = blockIdx.x;
    if (bid < 8192) {                 // LN1 -> g_x tf32
        int t = bid * 256 + threadIdx.x;
        float mu = g_stats[0], rs = g_stats[1];
        float4 m = ((const float4*)msa)[t];
        float4 ww = ((const float4*)w)[t];
        float4 bb = ((const float4*)b)[t];
        uint4 o;
        o.x = f2tf((m.x - mu) * rs * ww.x + bb.x);
        o.y = f2tf((m.y - mu) * rs * ww.y + bb.y);
        o.z = f2tf((m.z - mu) * rs * ww.z + bb.z);
        o.w = f2tf((m.w - mu) * rs * ww.w + bb.w);
        ((uint4*)g_x)[t] = o;
        return;
    }
    // pair bias blocks: 8192..8447
    __shared__ float wb_s[NH * CZ];
    int tid = threadIdx.x;
    for (int e = tid; e < NH * CZ; e += 256) wb_s[e] = Wb[e];
    __syncthreads();
    int col = (bid - 8192) * 256 + tid;
    float mu = g_stats[2], rs = g_stats[3];
    float acc[NH];
#pragma unroll
    for (int o = 0; o < NH; o++) acc[o] = 0.f;
#pragma unroll 4
    for (int c = 0; c < CZ; c++) {
        size_t idx = (size_t)c * IJ + col;
        float z = (pair[idx] - mu) * rs * ln2w[idx] + ln2b[idx];
#pragma unroll
        for (int o = 0; o < NH; o++) acc[o] += wb_s[o * CZ + c] * z;
    }
#pragma unroll
    for (int o = 0; o < NH; o++) g_bias[(size_t)o * IJ + col] = acc[o];
}

// ---------------- tf32 tensor-core GEMM: [M x 256] @ [256 x 32768] ----------
template<int MODE>
__global__ void __launch_bounds__(256) k_gemm(const float* __restrict__ bias,
                                              float* __restrict__ Cout) {
    __shared__ unsigned As[2][128][20];
    __shared__ unsigned Bs[2][16][136];

    const unsigned* A = MODE ? g_wstack : g_wrep;
    const unsigned* B = MODE ? g_x : (const unsigned*)g_o;
    float* C = MODE ? g_qkvg : Cout;

    const int tid = threadIdx.x;
    const int lane = tid & 31, warp = tid >> 5;
    const int wm = (warp & 1) * 64, wn = (warp >> 1) * 32;
    const int bm = blockIdx.y * 128, bn = blockIdx.x * 128;

    float acc[4][4][4];
#pragma unroll
    for (int i = 0; i < 4; i++)
#pragma unroll
        for (int j = 0; j < 4; j++)
#pragma unroll
            for (int k = 0; k < 4; k++) acc[i][j][k] = 0.f;

    unsigned sAb = (unsigned)__cvta_generic_to_shared(&As[0][0][0]);
    unsigned sBb = (unsigned)__cvta_generic_to_shared(&Bs[0][0][0]);

    auto load_tiles = [&](int buf, int k0) {
#pragma unroll
        for (int i = 0; i < 2; i++) {
            int idx = tid + i * 256;
            int row = idx >> 2, c4 = (idx & 3) << 2;
            cpa16(sAb + (((buf * 128 + row) * 20 + c4) << 2),
                  A + (size_t)(bm + row) * 256 + k0 + c4);
        }
#pragma unroll
        for (int i = 0; i < 2; i++) {
            int idx = tid + i * 256;
            int kk = idx >> 5, c4 = (idx & 31) << 2;
            cpa16(sBb + (((buf * 16 + kk) * 136 + c4) << 2),
                  B + (size_t)(k0 + kk) * NCOL + bn + c4);
        }
        asm volatile("cp.async.commit_group;" ::: "memory");
    };

    load_tiles(0, 0);
    int buf = 0;
    const int r = lane >> 2, cq = lane & 3;
    for (int it = 0; it < 16; it++) {
        asm volatile("cp.async.wait_group 0;" ::: "memory");
        __syncthreads();
        if (it < 15) load_tiles(buf ^ 1, (it + 1) * 16);
#pragma unroll
        for (int ks = 0; ks < 2; ks++) {
            int k8 = ks * 8;
            unsigned a[4][4], b[4][2];
#pragma unroll
            for (int mi = 0; mi < 4; mi++) {
                int rb = wm + mi * 16 + r;
                a[mi][0] = As[buf][rb][k8 + cq];
                a[mi][1] = As[buf][rb + 8][k8 + cq];
                a[mi][2] = As[buf][rb][k8 + cq + 4];
                a[mi][3] = As[buf][rb + 8][k8 + cq + 4];
            }
#pragma unroll
            for (int ni = 0; ni < 4; ni++) {
                int cb = wn + ni * 8 + r;
                b[ni][0] = Bs[buf][k8 + cq][cb];
                b[ni][1] = Bs[buf][k8 + 4 + cq][cb];
            }
#pragma unroll
            for (int mi = 0; mi < 4; mi++)
#pragma unroll
                for (int ni = 0; ni < 4; ni++)
                    mma_tf32(acc[mi][ni], a[mi][0], a[mi][1], a[mi][2], a[mi][3],
                             b[ni][0], b[ni][1]);
        }
        buf ^= 1;
    }

#pragma unroll
    for (int mi = 0; mi < 4; mi++) {
        int row = bm + wm + mi * 16 + r;
#pragma unroll
        for (int ni = 0; ni < 4; ni++) {
            int col = bn + wn + ni * 8 + 2 * cq;
            float v0 = acc[mi][ni][0], v1 = acc[mi][ni][1];
            float v2 = acc[mi][ni][2], v3 = acc[mi][ni][3];
            if (MODE == 1) {
                if (bm >= 768) {
                    float b0 = bias[row - 768], b8 = bias[row - 768 + 8];
                    v0 = 1.f / (1.f + __expf(-(v0 + b0)));
                    v1 = 1.f / (1.f + __expf(-(v1 + b0)));
                    v2 = 1.f / (1.f + __expf(-(v2 + b8)));
                    v3 = 1.f / (1.f + __expf(-(v3 + b8)));
                } else {
                    v0 = __uint_as_float(f2tf(v0));
                    v1 = __uint_as_float(f2tf(v1));
                    v2 = __uint_as_float(f2tf(v2));
                    v3 = __uint_as_float(f2tf(v3));
                }
            } else {
                float b0 = bias[row], b8 = bias[row + 8];
                v0 += b0; v1 += b0; v2 += b8; v3 += b8;
            }
            *(float2*)&C[(size_t)row * NCOL + col]       = make_float2(v0, v1);
            *(float2*)&C[(size_t)(row + 8) * NCOL + col] = make_float2(v2, v3);
        }
    }
}

// ---------------- attention: tf32 mma + ldmatrix, one block per (h, s) ------
// layouts (tf32 bits): qs [i][c] str 36, ks [j][c] str 36, vs [c][j] str 260,
//                      sc [64][j] str 260, os [c][i] str 68
#define QS_STR 36
#define KS_STR 36
#define VS_STR 260
#define SC_STR 260
#define OS_STR 68
#define ATTN_SMEM ((256*QS_STR + 256*KS_STR + 32*VS_STR + 64*SC_STR + 32*OS_STR) * 4)

__global__ void __launch_bounds__(512, 1) k_attn() {
    extern __shared__ unsigned smu[];
    unsigned* qs = smu;                       // [i][c]
    unsigned* ks = qs + 256 * QS_STR;         // [j][c]
    unsigned* vs = ks + 256 * KS_STR;         // [c][j]
    float*    sc = (float*)(vs + 32 * VS_STR);   // [64][SC_STR]
    float*    os = sc + 64 * SC_STR;          // [c][i]

    int s = blockIdx.x, h = blockIdx.y;
    int tid = threadIdx.x, lane = tid & 31, warp = tid >> 5;
    size_t colb = (size_t)s * 256;
    const unsigned* qg = (const unsigned*)g_qkvg;

    for (int e = tid; e < 8192; e += 512) {
        int c = e >> 8, i = e & 255;
        unsigned qv = qg[((size_t)(h * 32 + c)) * NCOL + colb + i];
        unsigned kv = qg[((size_t)(256 + h * 32 + c)) * NCOL + colb + i];
        unsigned vv = qg[((size_t)(512 + h * 32 + c)) * NCOL + colb + i];
        qs[i * QS_STR + c] = qv;
        ks[i * KS_STR + c] = kv;
        vs[c * VS_STR + i] = vv;
    }
    __syncthreads();

    const float scale = 0.17677669529663687f;   // 1/sqrt(32)
    const float* biasp = g_bias + (size_t)h * IJ;
    const int r = lane >> 2, cq = lane & 3;
    unsigned qs_sh = (unsigned)__cvta_generic_to_shared(qs);
    unsigned ks_sh = (unsigned)__cvta_generic_to_shared(ks);
    unsigned vs_sh = (unsigned)__cvta_generic_to_shared(vs);
    unsigned sc_sh = (unsigned)__cvta_generic_to_shared(sc);

    for (int i0 = 0; i0 < 256; i0 += 64) {
        // ---- prefetch 64x256 bias chunk into sc via cp.async ----
#pragma unroll
        for (int t = 0; t < 8; t++) {
            int idx = tid + t * 512;          // 0..4095 (float4 index)
            int row = idx >> 6, c4 = (idx & 63) << 2;
            cpa16(sc_sh + (unsigned)((row * SC_STR + c4) << 2),
                  biasp + (size_t)(i0 + row) * 256 + c4);
        }
        asm volatile("cp.async.commit_group;" ::: "memory");

        // ---- scores = Q K^T via mma: M=64(i), N=256(j), K=32(c) ----
        int wm2 = (warp & 3) * 16, wn2 = (warp >> 2) * 64;
        float acc[8][4];
#pragma unroll
        for (int ni = 0; ni < 8; ni++)
#pragma unroll
            for (int k = 0; k < 4; k++) acc[ni][k] = 0.f;
#pragma unroll
        for (int k16 = 0; k16 < 32; k16 += 16) {
            unsigned a0[4], a1[4];
            ldsm_x4(a0[0], a0[1], a0[2], a0[3], lds_addr_a(qs_sh, i0 + wm2, k16, QS_STR));
            ldsm_x4(a1[0], a1[1], a1[2], a1[3], lds_addr_a(qs_sh, i0 + wm2, k16 + 8, QS_STR));
#pragma unroll
            for (int ni = 0; ni < 8; ni++) {
                unsigned b[4];
                ldsm_x4(b[0], b[1], b[2], b[3], lds_addr_b(ks_sh, wn2 + ni * 8, k16, KS_STR));
                mma_tf32(acc[ni], a0[0], a0[1], a0[2], a0[3], b[0], b[1]);
                mma_tf32(acc[ni], a1[0], a1[1], a1[2], a1[3], b[2], b[3]);
            }
        }
        asm volatile("cp.async.wait_group 0;" ::: "memory");
        __syncthreads();
        // epilogue: scores*scale + preloaded bias (RMW in smem)
#pragma unroll
        for (int ni = 0; ni < 8; ni++) {
            int row = wm2 + r;
            int col = wn2 + ni * 8 + 2 * cq;
            float* p0 = &sc[row * SC_STR + col];
            float* p8 = &sc[(row + 8) * SC_STR + col];
            p0[0] = acc[ni][0] * scale + p0[0];
            p0[1] = acc[ni][1] * scale + p0[1];
            p8[0] = acc[ni][2] * scale + p8[0];
            p8[1] = acc[ni][3] * scale + p8[1];
        }
        __syncthreads();

        // ---- softmax (warp w: rows w*4..w*4+3); store tf32-rounded probs ----
#pragma unroll
        for (int rr = 0; rr < 4; rr++) {
            float* p = &sc[(warp * 4 + rr) * SC_STR];
            float vals[8];
            float m = -1e30f;
#pragma unroll
            for (int u = 0; u < 8; u++) { vals[u] = p[lane + u * 32]; m = fmaxf(m, vals[u]); }
#pragma unroll
            for (int off = 16; off; off >>= 1) m = fmaxf(m, __shfl_xor_sync(0xffffffffu, m, off));
            float sum = 0.f;
#pragma unroll
            for (int u = 0; u < 8; u++) { vals[u] = __expf(vals[u] - m); sum += vals[u]; }
#pragma unroll
            for (int off = 16; off; off >>= 1) sum += __shfl_xor_sync(0xffffffffu, sum, off);
            float inv = 1.f / sum;
#pragma unroll
            for (int u = 0; u < 8; u++) p[lane + u * 32] = __uint_as_float(f2tf(vals[u] * inv));
        }
        __syncthreads();

        // ---- AV via mma: M=64(i), N=32(c), K=256(j) ----
        {
            int am = (warp & 3) * 16, an = (warp >> 2) * 8;
            float av[4] = {0.f, 0.f, 0.f, 0.f};
#pragma unroll 4
            for (int k16 = 0; k16 < 256; k16 += 16) {
                unsigned a0[4], a1[4], b[4];
                ldsm_x4(a0[0], a0[1], a0[2], a0[3], lds_addr_a(sc_sh, am, k16, SC_STR));
                ldsm_x4(a1[0], a1[1], a1[2], a1[3], lds_addr_a(sc_sh, am, k16 + 8, SC_STR));
                ldsm_x4(b[0], b[1], b[2], b[3], lds_addr_b(vs_sh, an, k16, VS_STR));
                mma_tf32(av, a0[0], a0[1], a0[2], a0[3], b[0], b[1]);
                mma_tf32(av, a1[0], a1[1], a1[2], a1[3], b[2], b[3]);
            }
            int row = am + r, col = an + 2 * cq;
            os[col * OS_STR + row]           = av[0];
            os[(col + 1) * OS_STR + row]     = av[1];
            os[col * OS_STR + row + 8]       = av[2];
            os[(col + 1) * OS_STR + row + 8] = av[3];
        }
        __syncthreads();

        // ---- gate + store (coalesced over i), tf32-rounded for out GEMM ----
        for (int e = tid; e < 2048; e += 512) {
            int c2 = e >> 6, ii = e & 63;
            size_t col = colb + i0 + ii;
            float gv = g_qkvg[((size_t)(768 + h * 32 + c2)) * NCOL + col];
            float ov = os[c2 * OS_STR + ii] * gv;
            g_o[((size_t)(c2 * NH + h)) * NCOL + col] = __uint_as_float(f2tf(ov));
        }
        __syncthreads();
    }
}

// ---------------------------------------------------------------------------
extern "C" void kernel_launch(void* const* d_in, const int* in_sizes, int n_in,
                              void* d_out, int out_size) {
    const float* msa  = (const float*)d_in[0];
    const float* pair = (const float*)d_in[1];
    const float* ln1w = (const float*)d_in[2];
    const float* ln1b = (const float*)d_in[3];
    const float* ln2w = (const float*)d_in[4];
    const float* ln2b = (const float*)d_in[5];
    const float* Wq   = (const float*)d_in[6];
    const float* Wk   = (const float*)d_in[7];
    const float* Wv   = (const float*)d_in[8];
    const float* Wb   = (const float*)d_in[9];
    const float* Wg   = (const float*)d_in[10];
    const float* bg   = (const float*)d_in[11];
    const float* Wrep = (const float*)d_in[12];
    const float* brep = (const float*)d_in[13];
    float* out = (float*)d_out;

    // Opt-in to >48KB dynamic smem (set happens on the pre-capture call).
    cudaFuncAttributes attr;
    cudaFuncGetAttributes(&attr, k_attn);
    if (attr.maxDynamicSharedSizeBytes < (int)ATTN_SMEM) {
        cudaFuncSetAttribute(k_attn, cudaFuncAttributeMaxDynamicSharedMemorySize, ATTN_SMEM);
    }

    k_pre<<<2048 + 1280, 256>>>(msa, pair, Wq, Wk, Wv, Wg, Wrep);
    k_finalize<<<1, 1024>>>();
    k_ln1bias<<<8192 + 256, 256>>>(msa, ln1w, ln1b, pair, ln2w, ln2b, Wb);
    k_gemm<1><<<dim3(256, 8), 256>>>(bg, nullptr);
    k_attn<<<dim3(S_DIM, NH), 512, ATTN_SMEM>>>();
    k_gemm<0><<<dim3(256, 2), 256>>>(brep, out);
}